// round 17
// baseline (speedup 1.0000x reference)
#include <cuda_runtime.h>
#include <math.h>
#include <stdint.h>

// ---------------- problem constants ----------------
#define E_        8
#define NTOK      8192
#define D_        1024
#define F_        2816
#define NSLOT     (NTOK * 2)
#define SLOT_PAD  (NSLOT + E_ * 256)   // 18432, expert ranges 256-aligned
#define OUT_ELEMS (NTOK * D_)

#define BK    16                        // K per stage (two m16n8k8 halves)
#define NB    3                         // triple buffer, one sync/stage

// fragment-layout smem sizes (words)
#define ASTG1  2112                     // GEMM1 A: 16 groups x 132 (128 m)
#define BSTG1  4224                     // GEMM1 B: 64 blocks x 66 (256 n-slots)
#define STG1W  (ASTG1 + BSTG1)          // 6336 words
#define SMEM1  (NB * STG1W * 4)         // 76032 B

#define ASTG2  4224                     // GEMM2 A: 32 groups x 132 (256 m)
#define BSTG2  2112                     // GEMM2 B: 32 blocks x 66 (128 n)
#define STG2W  (ASTG2 + BSTG2)          // 6336 words
#define SMEM2  (NB * STG2W * 4)         // 76032 B

// ---------------- static device scratch ----------------
__device__ __align__(128) float g_act[(size_t)SLOT_PAD * F_];
__device__ __align__(128) float g_y2[(size_t)SLOT_PAD * D_];

__device__ int   g_perm_token[SLOT_PAD];
__device__ float g_perm_w[SLOT_PAD];
__device__ int   g_tok_slot[NSLOT];
__device__ int   g_counts[E_];
__device__ int   g_cursor[E_];
__device__ int   g_pad_off[E_ + 1];
__device__ int   g_topk_idx[NSLOT];
__device__ float g_topk_w[NSLOT];

// ---------------- tf32 mma helpers ----------------
static __device__ __forceinline__ uint32_t f2tf(float v) {
    uint32_t r;
    asm("cvt.rna.tf32.f32 %0, %1;" : "=r"(r) : "f"(v));
    return r;
}
static __device__ __forceinline__ void mma_tf32(float* d, const uint32_t* a, const uint32_t* b) {
    asm volatile("mma.sync.aligned.m16n8k8.row.col.f32.tf32.tf32.f32 "
                 "{%0,%1,%2,%3}, {%4,%5,%6,%7}, {%8,%9}, {%0,%1,%2,%3};"
                 : "+f"(d[0]), "+f"(d[1]), "+f"(d[2]), "+f"(d[3])
                 : "r"(a[0]), "r"(a[1]), "r"(a[2]), "r"(a[3]), "r"(b[0]), "r"(b[1]));
}

// ---------------- init ----------------
__global__ void init_kernel() {
    int i = blockIdx.x * 256 + threadIdx.x;
    if (i < SLOT_PAD) { g_perm_token[i] = -1; g_perm_w[i] = 0.0f; }
    if (i < E_) g_counts[i] = 0;
}

// ---------------- router / scan / fill ----------------
__global__ void router_kernel(const float* __restrict__ x, const float* __restrict__ rw) {
    int t = blockIdx.x;
    const float* xr = x + (size_t)t * D_;
    int lane = threadIdx.x & 31;
    int w    = threadIdx.x >> 5;

    double s = 0.0;
    for (int d = lane; d < D_; d += 32)
        s += (double)xr[d] * (double)rw[d * E_ + w];
    #pragma unroll
    for (int o = 16; o > 0; o >>= 1)
        s += __shfl_down_sync(0xffffffffu, s, o);

    __shared__ double sc[E_];
    if (lane == 0) sc[w] = s;
    __syncthreads();

    if (threadIdx.x == 0) {
        double m = sc[0];
        #pragma unroll
        for (int e = 1; e < E_; e++) m = fmax(m, sc[e]);
        double p[E_], sum = 0.0;
        #pragma unroll
        for (int e = 0; e < E_; e++) { p[e] = exp(sc[e] - m); sum += p[e]; }
        #pragma unroll
        for (int e = 0; e < E_; e++) p[e] /= sum;
        int i0 = 0;
        #pragma unroll
        for (int e = 1; e < E_; e++) if (p[e] > p[i0]) i0 = e;
        int i1 = (i0 == 0) ? 1 : 0;
        #pragma unroll
        for (int e = 0; e < E_; e++) { if (e == i0) continue; if (p[e] > p[i1]) i1 = e; }
        float p0 = (float)p[i0], p1 = (float)p[i1];
        float inv = 1.0f / (p0 + p1);
        g_topk_idx[t * 2 + 0] = i0;  g_topk_idx[t * 2 + 1] = i1;
        g_topk_w[t * 2 + 0] = p0 * inv;  g_topk_w[t * 2 + 1] = p1 * inv;
        atomicAdd(&g_counts[i0], 1);
        atomicAdd(&g_counts[i1], 1);
    }
}

__global__ void scan_kernel() {
    int off = 0;
    #pragma unroll
    for (int e = 0; e < E_; e++) {
        g_pad_off[e] = off;  g_cursor[e] = off;
        off += (g_counts[e] + 255) & ~255;
    }
    g_pad_off[E_] = off;
}

__global__ void fill_kernel() {
    int idx = blockIdx.x * blockDim.x + threadIdx.x;
    if (idx >= NSLOT) return;
    int e    = g_topk_idx[idx];
    int slot = atomicAdd(&g_cursor[e], 1);
    g_perm_token[slot] = idx >> 1;
    g_perm_w[slot]     = g_topk_w[idx];
    g_tok_slot[idx]    = slot;
}

// ---------------- fragment-layout store helpers ----------------
// A value (m,k): group=(k>>3)*GROWS+(m>>4); lane=4*(m&7)+(k&3);
//   line=lane^(lane>>3); q=((m>>3)&1)+2*((k>>2)&1); addr=group*132+line*4+q
template <int GROWS>
static __device__ __forceinline__ void store_a4(uint32_t* An, int am, int ak4,
                                                const float* a) {
    int g0 = ((ak4 >> 3) * GROWS + (am >> 4)) * 132;
    int q  = ((am >> 3) & 1) + 2 * ((ak4 >> 2) & 1);
    int lb = 4 * (am & 7);
    #pragma unroll
    for (int j = 0; j < 4; j++) {
        int lane = lb + j;
        int line = lane ^ (lane >> 3);
        An[g0 + line * 4 + q] = f2tf(a[j]);
    }
}
// B (two k rows bkr, bkr+8; slots ns0..ns0+3); HS = words per k-half
static __device__ __forceinline__ void store_b8(uint32_t* Bn, int bkr, int ns0,
                                                const float* b0, const float* b1,
                                                int HS) {
    int klow = bkr & 3;
    int cB   = bkr >> 2;
    #pragma unroll
    for (int t = 0; t < 4; t++) {
        int ns   = ns0 + t;
        int lane = 4 * (ns & 7) + klow;
        int blk  = (ns >> 3) * 66;
        Bn[blk + 2 * lane + cB]      = f2tf(b0[t]);
        Bn[HS + blk + 2 * lane + cB] = f2tf(b1[t]);
    }
}
// B single k row bk (0..15), slots ns0..ns0+3; HS = words per k-half
static __device__ __forceinline__ void store_b4(uint32_t* Bn, int bk, int ns0,
                                                const float* b, int HS) {
    int klow = bk & 3;
    int cB   = (bk >> 2) & 1;
    int half = bk >> 3;
    #pragma unroll
    for (int t = 0; t < 4; t++) {
        int ns   = ns0 + t;
        int lane = 4 * (ns & 7) + klow;
        int blk  = (ns >> 3) * 66;
        Bn[half * HS + blk + 2 * lane + cB] = f2tf(b[t]);
    }
}

// =====================================================================
// GEMM1 (tf32 mma): act = silu(x@G) * (x@U)   [R16-proven]
// CTA 128m x 128f (B: 256 n-slots = gate|up). 512 threads, 16 warps.
// =====================================================================
__global__ __launch_bounds__(512, 1)
void gemm1_mma(const float* __restrict__ x,
               const float* __restrict__ gate_w,
               const float* __restrict__ up_w) {
    int row0 = blockIdx.y * 128;
    if (row0 >= g_pad_off[E_]) return;
    int e = 0;
    while (e < E_ - 1 && g_pad_off[e + 1] <= row0) e++;
    int f0  = blockIdx.x * 128;
    int tid = threadIdx.x, wid = tid >> 5, lane = tid & 31;
    int wm = wid >> 2, wn = wid & 3;

    extern __shared__ uint32_t dyn[];

    int am  = tid >> 2;
    int ak4 = (tid & 3) * 4;
    int tok = g_perm_token[row0 + am];
    bool valid = (tok >= 0);
    const float* pa = x + (size_t)(valid ? tok : 0) * D_ + ak4;

    int bkr = tid >> 6;
    int bn4 = (tid & 63) * 4;
    const float* pb = (bn4 < 128)
        ? gate_w + ((size_t)e * D_ + bkr) * F_ + f0 + bn4
        : up_w   + ((size_t)e * D_ + bkr) * F_ + f0 + (bn4 - 128);

    float accG[2][4][4], accU[2][4][4];
    #pragma unroll
    for (int i = 0; i < 2; i++)
        #pragma unroll
        for (int j = 0; j < 4; j++)
            #pragma unroll
            for (int q = 0; q < 4; q++) { accG[i][j][q] = 0.f; accU[i][j][q] = 0.f; }

    const int NS = D_ / BK;   // 64

    float4 rA, rB0, rB1;
    rA  = valid ? *(const float4*)pa : make_float4(0, 0, 0, 0);
    rB0 = *(const float4*)pb;
    rB1 = *(const float4*)(pb + (size_t)8 * F_);
    store_a4<8>(dyn, am, ak4, (const float*)&rA);
    store_b8(dyn + ASTG1, bkr, bn4, (const float*)&rB0, (const float*)&rB1, 32 * 66);
    rA  = valid ? *(const float4*)(pa + BK) : make_float4(0, 0, 0, 0);
    rB0 = *(const float4*)(pb + (size_t)BK * F_);
    rB1 = *(const float4*)(pb + (size_t)(BK + 8) * F_);
    __syncthreads();

    int lineoff = (lane ^ (lane >> 3)) * 4;
    int boff    = 2 * lane;

    #pragma unroll 1
    for (int s = 0; s < NS; s++) {
        int cb = s % NB;
        if (s + 1 < NS) {
            uint32_t* stg = dyn + ((s + 1) % NB) * STG1W;
            store_a4<8>(stg, am, ak4, (const float*)&rA);
            store_b8(stg + ASTG1, bkr, bn4, (const float*)&rB0, (const float*)&rB1, 32 * 66);
        }
        if (s + 2 < NS) {
            int k0 = (s + 2) * BK;
            rA  = valid ? *(const float4*)(pa + k0) : make_float4(0, 0, 0, 0);
            rB0 = *(const float4*)(pb + (size_t)k0 * F_);
            rB1 = *(const float4*)(pb + (size_t)(k0 + 8) * F_);
        }
        __syncthreads();

        const uint32_t* A = dyn + cb * STG1W;
        const uint32_t* B = A + ASTG1;
        #pragma unroll
        for (int h = 0; h < 2; h++) {
            uint4 af[2];
            #pragma unroll
            for (int i = 0; i < 2; i++)
                af[i] = *(const uint4*)&A[(h * 8 + 2 * wm + i) * 132 + lineoff];
            #pragma unroll
            for (int j = 0; j < 4; j++) {
                uint2 bgv = *(const uint2*)&B[(h * 32 + 4 * wn + j) * 66 + boff];
                uint2 buv = *(const uint2*)&B[(h * 32 + 16 + 4 * wn + j) * 66 + boff];
                #pragma unroll
                for (int i = 0; i < 2; i++) {
                    mma_tf32(accG[i][j], (const uint32_t*)&af[i], (const uint32_t*)&bgv);
                    mma_tf32(accU[i][j], (const uint32_t*)&af[i], (const uint32_t*)&buv);
                }
            }
        }
    }

    #pragma unroll
    for (int i = 0; i < 2; i++)
        #pragma unroll
        for (int j = 0; j < 4; j++) {
            int fb = f0 + 32 * wn + 8 * j + 2 * (lane & 3);
            #pragma unroll
            for (int h = 0; h < 2; h++) {
                int row = row0 + 32 * wm + 16 * i + (lane >> 2) + 8 * h;
                float g0 = accG[i][j][2 * h + 0], g1 = accG[i][j][2 * h + 1];
                float u0 = accU[i][j][2 * h + 0], u1 = accU[i][j][2 * h + 1];
                float2 o;
                o.x = (g0 / (1.0f + __expf(-g0))) * u0;
                o.y = (g1 / (1.0f + __expf(-g1))) * u1;
                *(float2*)(g_act + (size_t)row * F_ + fb) = o;
            }
        }
}

// =====================================================================
// GEMM2 (tf32 mma): y2 = w * (act @ Wdown)
// CTA 256m x 128n. 512 threads, 16 warps: wm=wid>>2 (64m), wn=wid&3 (32n).
// =====================================================================
__global__ __launch_bounds__(512, 1)
void gemm2_mma(const float* __restrict__ down_w) {
    int row0 = blockIdx.y * 256;
    if (row0 >= g_pad_off[E_]) return;
    int e = 0;
    while (e < E_ - 1 && g_pad_off[e + 1] <= row0) e++;
    int n0  = blockIdx.x * 128;
    int tid = threadIdx.x, wid = tid >> 5, lane = tid & 31;
    int wm = wid >> 2, wn = wid & 3;

    extern __shared__ uint32_t dyn[];

    // A loader: am = tid>>1 (0..255), akq = (tid&1)*4; two float4 (k, k+8)
    int am  = tid >> 1;
    int akq = (tid & 1) * 4;
    const float* pa = g_act + (size_t)(row0 + am) * F_ + akq;

    // B loader: bk = tid>>5 (0..15), bn4 = (tid&31)*4; one float4
    int bk  = tid >> 5;
    int bn4 = (tid & 31) * 4;
    const float* pb = down_w + ((size_t)e * F_ + bk) * D_ + n0 + bn4;

    float acc[4][4][4];
    #pragma unroll
    for (int i = 0; i < 4; i++)
        #pragma unroll
        for (int j = 0; j < 4; j++)
            #pragma unroll
            for (int q = 0; q < 4; q++) acc[i][j][q] = 0.f;

    const int NS = F_ / BK;   // 176

    float4 rA0, rA1, rB;
    rA0 = *(const float4*)pa;
    rA1 = *(const float4*)(pa + 8);
    rB  = *(const float4*)pb;
    store_a4<16>(dyn, am, akq, (const float*)&rA0);
    store_a4<16>(dyn, am, akq + 8, (const float*)&rA1);
    store_b4(dyn + ASTG2, bk, bn4, (const float*)&rB, 16 * 66);
    rA0 = *(const float4*)(pa + BK);
    rA1 = *(const float4*)(pa + BK + 8);
    rB  = *(const float4*)(pb + (size_t)BK * D_);
    __syncthreads();

    int lineoff = (lane ^ (lane >> 3)) * 4;
    int boff    = 2 * lane;

    #pragma unroll 1
    for (int s = 0; s < NS; s++) {
        int cb = s % NB;
        if (s + 1 < NS) {
            uint32_t* stg = dyn + ((s + 1) % NB) * STG2W;
            store_a4<16>(stg, am, akq, (const float*)&rA0);
            store_a4<16>(stg, am, akq + 8, (const float*)&rA1);
            store_b4(stg + ASTG2, bk, bn4, (const float*)&rB, 16 * 66);
        }
        if (s + 2 < NS) {
            int k0 = (s + 2) * BK;
            rA0 = *(const float4*)(pa + k0);
            rA1 = *(const float4*)(pa + k0 + 8);
            rB  = *(const float4*)(pb + (size_t)k0 * D_);
        }
        __syncthreads();

        const uint32_t* A = dyn + cb * STG2W;
        const uint32_t* B = A + ASTG2;
        #pragma unroll
        for (int h = 0; h < 2; h++) {
            uint4 af[4];
            #pragma unroll
            for (int i = 0; i < 4; i++)
                af[i] = *(const uint4*)&A[(h * 16 + 4 * wm + i) * 132 + lineoff];
            #pragma unroll
            for (int j = 0; j < 4; j++) {
                uint2 bv = *(const uint2*)&B[(h * 16 + 4 * wn + j) * 66 + boff];
                #pragma unroll
                for (int i = 0; i < 4; i++)
                    mma_tf32(acc[i][j], (const uint32_t*)&af[i], (const uint32_t*)&bv);
            }
        }
    }

    #pragma unroll
    for (int i = 0; i < 4; i++)
        #pragma unroll
        for (int h = 0; h < 2; h++) {
            int row = row0 + 64 * wm + 16 * i + (lane >> 2) + 8 * h;
            float w = g_perm_w[row];
            #pragma unroll
            for (int j = 0; j < 4; j++) {
                int nn = n0 + 32 * wn + 8 * j + 2 * (lane & 3);
                float2 v;
                v.x = acc[i][j][2 * h + 0] * w;
                v.y = acc[i][j][2 * h + 1] * w;
                *(float2*)(g_y2 + (size_t)row * D_ + nn) = v;
            }
        }
}

// ---------------- combine ----------------
__global__ void combine_kernel(float* __restrict__ out) {
    int i = blockIdx.x * 256 + threadIdx.x;
    if (i >= OUT_ELEMS) return;
    int t = i >> 10, d = i & 1023;
    int s0 = g_tok_slot[t * 2 + 0];
    int s1 = g_tok_slot[t * 2 + 1];
    out[i] = g_y2[(size_t)s0 * D_ + d] + g_y2[(size_t)s1 * D_ + d];
}

// ---------------- launch ----------------
extern "C" void kernel_launch(void* const* d_in, const int* in_sizes, int n_in,
                              void* d_out, int out_size) {
    const float* x      = (const float*)d_in[0];
    const float* rw     = (const float*)d_in[1];
    const float* gate_w = (const float*)d_in[2];
    const float* up_w   = (const float*)d_in[3];
    const float* down_w = (const float*)d_in[4];
    float* out = (float*)d_out;

    static int smem_set = 0;
    if (!smem_set) {
        cudaFuncSetAttribute(gemm1_mma, cudaFuncAttributeMaxDynamicSharedMemorySize, SMEM1);
        cudaFuncSetAttribute(gemm2_mma, cudaFuncAttributeMaxDynamicSharedMemorySize, SMEM2);
        smem_set = 1;
    }

    init_kernel<<<(SLOT_PAD + 255) / 256, 256>>>();
    router_kernel<<<NTOK, 256>>>(x, rw);
    scan_kernel<<<1, 1>>>();
    fill_kernel<<<(NSLOT + 255) / 256, 256>>>();

    dim3 g1(F_ / 128, SLOT_PAD / 128);   // 22 x 144
    gemm1_mma<<<g1, 512, SMEM1>>>(x, gate_w, up_w);

    dim3 g2(D_ / 128, SLOT_PAD / 256);   // 8 x 72
    gemm2_mma<<<g2, 512, SMEM2>>>(down_w);

    combine_kernel<<<(OUT_ELEMS + 255) / 256, 256>>>(out);
}